// round 16
// baseline (speedup 1.0000x reference)
#include <cuda_runtime.h>
#include <math.h>

#define NP_MAX     1048576
#define TABLE_SIZE 524288
#define TMASK      (TABLE_SIZE - 1)
#define NUM_LEVELS 8
#define W0F        30.0f
#define NSM        148

#define TPB1       512
#define WARPS1     (TPB1 / 32)
#define TPB2       512
#define WARPS2     (TPB2 / 32)
#define XS1        68   // 17 odd 16B-chunks: conflict-free; >= 64 (layer outputs!)
#define XS2        68   // MUST be >= 64: hidden layers write 64 cols back into xs

typedef unsigned long long u64t;

// Encoding scratch, SoA: g_enc[c*N + n], c in [0,32)  (written by mlp1, read by mlp2)
__device__ float g_enc[NUM_LEVELS * 4 * NP_MAX];
// siren1 head output (o[0..15]) per point, lane-owned float4 chunks
__device__ float4 g_mid[NP_MAX * 4];

struct Res8 { float r[8]; };

// ---------------------------------------------------------------------------
// Packed f32x2 helpers (PTX-only; ptxas never auto-fuses FFMA2).
// ---------------------------------------------------------------------------
__device__ __forceinline__ u64t pack2(float x) {
    u64t r; unsigned xi = __float_as_uint(x);
    asm("mov.b64 %0, {%1, %1};" : "=l"(r) : "r"(xi));
    return r;
}
__device__ __forceinline__ u64t ffma2(u64t a, u64t b, u64t c) {
    u64t d;
    asm("fma.rn.f32x2 %0, %1, %2, %3;" : "=l"(d) : "l"(a), "l"(b), "l"(c));
    return d;
}
__device__ __forceinline__ float2 unpack2(u64t v) {
    unsigned lo, hi;
    asm("mov.b64 {%0, %1}, %2;" : "=r"(lo), "=r"(hi) : "l"(v));
    return make_float2(__uint_as_float(lo), __uint_as_float(hi));
}

// ---------------------------------------------------------------------------
// Accurate sin, ~1-2 ulp RELATIVE accuracy. Fast path: magic-number rounding
// (bit-identical q to rintf(x*INV_PI) for |q| < 2^22) + parity from mantissa
// lsb applied as sign-bit XOR (bit-identical to conditional negate).
// ---------------------------------------------------------------------------
__device__ __forceinline__ float sin_acc(float x) {
    const float INV_PI = 0.318309886183790672f;
    const float PI_HI  = 3.14159274101257324f;
    const float PI_LO  = -8.74227765734758577e-8f;
    const float MAGIC  = 12582912.0f;            // 1.5 * 2^23
    float t = __fadd_rn(__fmul_rn(x, INV_PI), MAGIC);
    unsigned sgn = __float_as_uint(t) << 31;     // parity of q -> sign bit
    float q = t - MAGIC;                         // == rintf(x * INV_PI)
    float r = fmaf(-q, PI_HI, x);
    r = fmaf(-q, PI_LO, r);
    float r2 = r * r;
    float p = 1.58969104521e-10f;
    p = fmaf(p, r2, -2.50507477726e-8f);
    p = fmaf(p, r2, 2.75573146014e-6f);
    p = fmaf(p, r2, -1.98412701138e-4f);
    p = fmaf(p, r2, 8.33333376795e-3f);
    p = fmaf(p, r2, -1.66666671634e-1f);
    float s = fmaf(p * r2, r, r);
    return __uint_as_float(__float_as_uint(s) ^ sgn);
}

// ---------------------------------------------------------------------------
// Inline Instant-NGP hash encoding for ONE point; writes the 32 features to
// row[] (xs) and to g_enc (for mlp2). Identical arithmetic to the previous
// standalone hash_kernel.
// ---------------------------------------------------------------------------
__device__ __forceinline__ void hash_point(const float* __restrict__ pts,
                                           const float* __restrict__ table,
                                           int N, int n, const Res8& R,
                                           float* __restrict__ row) {
    float px = (pts[3 * n + 0] + 1.0f) * 0.5f;
    float py = (pts[3 * n + 1] + 1.0f) * 0.5f;
    float pz = (pts[3 * n + 2] + 1.0f) * 0.5f;
    const float4* tab4 = (const float4*)table;
#pragma unroll 1
    for (int l = 0; l < NUM_LEVELS; l++) {
        float res = R.r[l];
        float sx = px * res, sy = py * res, sz = pz * res;
        float bx = floorf(sx), by = floorf(sy), bz = floorf(sz);
        float fx = sx - bx, fy = sy - by, fz = sz - bz;
        int ix = (int)bx, iy = (int)by, iz = (int)bz;
        unsigned hx0 = (unsigned)ix;
        unsigned hx1 = (unsigned)(ix + 1);
        unsigned hy0 = (unsigned)iy       * 2654435761u;
        unsigned hy1 = (unsigned)(iy + 1) * 2654435761u;
        unsigned hz0 = (unsigned)iz       * 805459861u;
        unsigned hz1 = (unsigned)(iz + 1) * 805459861u;
        const float4* t = tab4 + (size_t)l * TABLE_SIZE;
        float4 g000 = t[(hx0 ^ hy0 ^ hz0) & TMASK];
        float4 g001 = t[(hx0 ^ hy0 ^ hz1) & TMASK];
        float4 g010 = t[(hx0 ^ hy1 ^ hz0) & TMASK];
        float4 g011 = t[(hx0 ^ hy1 ^ hz1) & TMASK];
        float4 g100 = t[(hx1 ^ hy0 ^ hz0) & TMASK];
        float4 g101 = t[(hx1 ^ hy0 ^ hz1) & TMASK];
        float4 g110 = t[(hx1 ^ hy1 ^ hz0) & TMASK];
        float4 g111 = t[(hx1 ^ hy1 ^ hz1) & TMASK];
        float ux = 1.0f - fx, uy = 1.0f - fy, uz = 1.0f - fz;
        float w000 = ux * uy * uz, w001 = ux * uy * fz;
        float w010 = ux * fy * uz, w011 = ux * fy * fz;
        float w100 = fx * uy * uz, w101 = fx * uy * fz;
        float w110 = fx * fy * uz, w111 = fx * fy * fz;
        float a0 = w000 * g000.x + w001 * g001.x + w010 * g010.x + w011 * g011.x
                 + w100 * g100.x + w101 * g101.x + w110 * g110.x + w111 * g111.x;
        float a1 = w000 * g000.y + w001 * g001.y + w010 * g010.y + w011 * g011.y
                 + w100 * g100.y + w101 * g101.y + w110 * g110.y + w111 * g111.y;
        float a2 = w000 * g000.z + w001 * g001.z + w010 * g010.z + w011 * g011.z
                 + w100 * g100.z + w101 * g101.z + w110 * g110.z + w111 * g111.z;
        float a3 = w000 * g000.w + w001 * g001.w + w010 * g010.w + w011 * g011.w
                 + w100 * g100.w + w101 * g101.w + w110 * g110.w + w111 * g111.w;
        row[l * 4 + 0] = a0;
        row[l * 4 + 1] = a1;
        row[l * 4 + 2] = a2;
        row[l * 4 + 3] = a3;
        g_enc[(size_t)(l * 4 + 0) * N + n] = a0;
        g_enc[(size_t)(l * 4 + 1) * N + n] = a1;
        g_enc[(size_t)(l * 4 + 2) * N + n] = a2;
        g_enc[(size_t)(l * 4 + 3) * N + n] = a3;
    }
}

// ---------------------------------------------------------------------------
// Warp-tiled layer: warp = 32 points x 64 outputs.
// Lane (pg, jg): points {pg, pg+8, pg+16, pg+24}, outputs [16*jg, 16*jg+16).
// ---------------------------------------------------------------------------
template <int IN4, int STRIDE>
__device__ __forceinline__ void layer_tiled(const float* __restrict__ W,
                                            const float* __restrict__ B,
                                            float* __restrict__ xs,
                                            int pg, int jg, float scale) {
    u64t acc[4][8];
    {
        const ulonglong2* bb = (const ulonglong2*)(B + 16 * jg);
#pragma unroll
        for (int m = 0; m < 4; m++) {
            ulonglong2 b = bb[m];
#pragma unroll
            for (int k = 0; k < 4; k++) {
                acc[k][2 * m]     = b.x;
                acc[k][2 * m + 1] = b.y;
            }
        }
    }
    const float* wbase = W + 16 * jg;
    const float* x0p = xs + pg * STRIDE;
#pragma unroll 2
    for (int i4 = 0; i4 < IN4; i4++) {
        float4 xv[4];
#pragma unroll
        for (int k = 0; k < 4; k++)
            xv[k] = *(const float4*)(x0p + k * 8 * STRIDE + 4 * i4);
#pragma unroll
        for (int ii = 0; ii < 4; ii++) {
            const ulonglong2* wp = (const ulonglong2*)(wbase + (4 * i4 + ii) * 64);
            ulonglong2 wA = wp[0], wB = wp[1], wC = wp[2], wD = wp[3];
#pragma unroll
            for (int k = 0; k < 4; k++) {
                u64t x2 = pack2(((const float*)&xv[k])[ii]);
                acc[k][0] = ffma2(x2, wA.x, acc[k][0]);
                acc[k][1] = ffma2(x2, wA.y, acc[k][1]);
                acc[k][2] = ffma2(x2, wB.x, acc[k][2]);
                acc[k][3] = ffma2(x2, wB.y, acc[k][3]);
                acc[k][4] = ffma2(x2, wC.x, acc[k][4]);
                acc[k][5] = ffma2(x2, wC.y, acc[k][5]);
                acc[k][6] = ffma2(x2, wD.x, acc[k][6]);
                acc[k][7] = ffma2(x2, wD.y, acc[k][7]);
            }
        }
    }
    __syncwarp();
#pragma unroll
    for (int k = 0; k < 4; k++) {
        float* row = xs + (pg + 8 * k) * STRIDE + 16 * jg;
#pragma unroll
        for (int m = 0; m < 4; m++) {
            float2 v0 = unpack2(acc[k][2 * m]);
            float2 v1 = unpack2(acc[k][2 * m + 1]);
            float4 r;
            r.x = sin_acc(scale * v0.x);
            r.y = sin_acc(scale * v0.y);
            r.z = sin_acc(scale * v1.x);
            r.w = sin_acc(scale * v1.y);
            *(float4*)(row + 4 * m) = r;
        }
    }
    __syncwarp();
}

// SIREN1 head: 64 -> 16, no activation. Lane owns outputs [4jg, 4jg+4).
template <int STRIDE>
__device__ __forceinline__ void head16_tiled(const float* __restrict__ W,
                                             const float* __restrict__ B,
                                             const float* __restrict__ xs,
                                             int pg, int jg, float o[4][4]) {
    u64t acc[4][2];
    {
        const ulonglong2* bb = (const ulonglong2*)(B + 4 * jg);
        ulonglong2 b = bb[0];
#pragma unroll
        for (int k = 0; k < 4; k++) { acc[k][0] = b.x; acc[k][1] = b.y; }
    }
    const float* x0p = xs + pg * STRIDE;
#pragma unroll 2
    for (int i4 = 0; i4 < 16; i4++) {
        float4 xv[4];
#pragma unroll
        for (int k = 0; k < 4; k++)
            xv[k] = *(const float4*)(x0p + k * 8 * STRIDE + 4 * i4);
#pragma unroll
        for (int ii = 0; ii < 4; ii++) {
            const ulonglong2* wp = (const ulonglong2*)(W + (4 * i4 + ii) * 16 + 4 * jg);
            ulonglong2 w = wp[0];
#pragma unroll
            for (int k = 0; k < 4; k++) {
                u64t x2 = pack2(((const float*)&xv[k])[ii]);
                acc[k][0] = ffma2(x2, w.x, acc[k][0]);
                acc[k][1] = ffma2(x2, w.y, acc[k][1]);
            }
        }
    }
#pragma unroll
    for (int k = 0; k < 4; k++) {
        float2 v0 = unpack2(acc[k][0]);
        float2 v1 = unpack2(acc[k][1]);
        o[k][0] = v0.x; o[k][1] = v0.y; o[k][2] = v1.x; o[k][3] = v1.y;
    }
}

// ---------------------------------------------------------------------------
// Kernel 1: fused hash + SIREN 1. Writes g_enc, g_mid, density.
// ---------------------------------------------------------------------------
#define O1_W1IN  0        // 32*64 = 2048
#define O1_B1IN  2048     // 64
#define O1_W1H   2112     // 4*64*64 = 16384
#define O1_B1H   18496    // 4*64 = 256
#define O1_W1OUT 18752    // 64*16 = 1024
#define O1_B1OUT 19776    // 16
#define O1_XS    19792
#define SM1_BYTES ((O1_XS + WARPS1 * 32 * XS1) * sizeof(float))

__global__ void __launch_bounds__(TPB1, 1) mlp1_kernel(
    const float* __restrict__ pts,     const float* __restrict__ table,
    const float* __restrict__ s1_win,  const float* __restrict__ s1_bin,
    const float* __restrict__ s1_wh,   const float* __restrict__ s1_bh,
    const float* __restrict__ s1_wout, const float* __restrict__ s1_bout,
    float* __restrict__ out, int N, Res8 R) {
    extern __shared__ float sm[];
    int tid = threadIdx.x;
#define CPY(off, src, cnt) \
    for (int i = tid; i < (cnt); i += TPB1) sm[(off) + i] = (src)[i];
    CPY(O1_W1IN,  s1_win,  2048);
    CPY(O1_B1IN,  s1_bin,  64);
    CPY(O1_W1H,   s1_wh,   16384);
    CPY(O1_B1H,   s1_bh,   256);
    CPY(O1_W1OUT, s1_wout, 1024);
    CPY(O1_B1OUT, s1_bout, 16);
#undef CPY
    __syncthreads();

    int wid  = tid >> 5;
    int lane = tid & 31;
    int pg = lane & 7;
    int jg = lane >> 3;
    float* xs = sm + O1_XS + wid * (32 * XS1);

    int ntiles = (N + 31) >> 5;
    for (int t = blockIdx.x * WARPS1 + wid; t < ntiles; t += NSM * WARPS1) {
        int nb = t << 5;

        // Fused hash: lane computes full encoding for its row point,
        // filling xs cols 0..31 and g_enc (consumed later by mlp2).
        {
            int nl = min(nb + lane, N - 1);
            hash_point(pts, table, N, nl, R, xs + lane * XS1);
        }
        __syncwarp();

        layer_tiled<8, XS1>(sm + O1_W1IN, sm + O1_B1IN, xs, pg, jg, W0F);
#pragma unroll
        for (int l = 0; l < 4; l++)
            layer_tiled<16, XS1>(sm + O1_W1H + l * 4096, sm + O1_B1H + l * 64,
                                 xs, pg, jg, 1.0f);

        float o[4][4];
        head16_tiled<XS1>(sm + O1_W1OUT, sm + O1_B1OUT, xs, pg, jg, o);

#pragma unroll
        for (int k = 0; k < 4; k++) {
            int n = nb + pg + 8 * k;
            if (n < N) {
                g_mid[(size_t)n * 4 + jg] =
                    make_float4(o[k][0], o[k][1], o[k][2], o[k][3]);
                if (jg == 0) out[N + n] = fmaxf(o[k][0], 0.0f);
            }
        }
        __syncwarp();
    }
}

// ---------------------------------------------------------------------------
// Kernel 2: SIREN 2 ([o1..15, enc32, 0pad] -> 64 -> 2x64 -> 1). Writes scalar.
// ---------------------------------------------------------------------------
#define O2_W2IN  0        // 48*64 = 3072 (row 47 zero-padded)
#define O2_B2IN  3072     // 64
#define O2_W2H   3136     // 2*64*64 = 8192
#define O2_B2H   11328    // 128
#define O2_W2OUT 11456    // 64
#define O2_B2OUT 11520    // 1 (+3 pad)
#define O2_XS    11524
#define SM2_BYTES ((O2_XS + WARPS2 * 32 * XS2) * sizeof(float))

__global__ void __launch_bounds__(TPB2, 1) mlp2_kernel(
    const float* __restrict__ s2_win,  const float* __restrict__ s2_bin,
    const float* __restrict__ s2_wh,   const float* __restrict__ s2_bh,
    const float* __restrict__ s2_wout, const float* __restrict__ s2_bout,
    float* __restrict__ out, int N) {
    extern __shared__ float sm[];
    int tid = threadIdx.x;
#define CPY(off, src, cnt) \
    for (int i = tid; i < (cnt); i += TPB2) sm[(off) + i] = (src)[i];
    CPY(O2_W2IN,  s2_win,  3008);
    CPY(O2_B2IN,  s2_bin,  64);
    CPY(O2_W2H,   s2_wh,   8192);
    CPY(O2_B2H,   s2_bh,   128);
    CPY(O2_W2OUT, s2_wout, 64);
    CPY(O2_B2OUT, s2_bout, 1);
#undef CPY
    for (int i = tid; i < 64; i += TPB2) sm[O2_W2IN + 47 * 64 + i] = 0.0f;
    __syncthreads();

    int wid  = tid >> 5;
    int lane = tid & 31;
    int pg = lane & 7;
    int jg = lane >> 3;
    float* xs = sm + O2_XS + wid * (32 * XS2);

    int ntiles = (N + 31) >> 5;
    for (int t = blockIdx.x * WARPS2 + wid; t < ntiles; t += NSM * WARPS2) {
        int nb = t << 5;

        // cols 0..14: o[1..15] from g_mid (lane reads its own chunk)
#pragma unroll
        for (int k = 0; k < 4; k++) {
            int n = min(nb + pg + 8 * k, N - 1);
            float4 v = g_mid[(size_t)n * 4 + jg];
            float* row = xs + (pg + 8 * k) * XS2;
            float vv[4] = {v.x, v.y, v.z, v.w};
#pragma unroll
            for (int c = 0; c < 4; c++) {
                int j = 4 * jg + c;
                if (j >= 1) row[j - 1] = vv[c];
            }
        }
        // cols 15..46: enc; col 47: 0
        {
            int nl = min(nb + lane, N - 1);
            float* row = xs + lane * XS2;
#pragma unroll
            for (int c = 0; c < 32; c++) row[15 + c] = g_enc[(size_t)c * N + nl];
            row[47] = 0.0f;
        }
        __syncwarp();

        layer_tiled<12, XS2>(sm + O2_W2IN, sm + O2_B2IN, xs, pg, jg, W0F);
#pragma unroll
        for (int l = 0; l < 2; l++)
            layer_tiled<16, XS2>(sm + O2_W2H + l * 4096, sm + O2_B2H + l * 64,
                                 xs, pg, jg, 1.0f);

        // 64 -> 1: lane sums i in [16jg,16jg+16), butterfly across jg lanes
        float part[4] = {0.0f, 0.0f, 0.0f, 0.0f};
        const float* wv  = sm + O2_W2OUT + 16 * jg;
        const float* x0p = xs + pg * XS2 + 16 * jg;
#pragma unroll
        for (int q = 0; q < 4; q++) {
            float4 w = *(const float4*)(wv + 4 * q);
#pragma unroll
            for (int k = 0; k < 4; k++) {
                float4 x = *(const float4*)(x0p + k * 8 * XS2 + 4 * q);
                part[k] = fmaf(x.x, w.x, part[k]);
                part[k] = fmaf(x.y, w.y, part[k]);
                part[k] = fmaf(x.z, w.z, part[k]);
                part[k] = fmaf(x.w, w.w, part[k]);
            }
        }
#pragma unroll
        for (int k = 0; k < 4; k++) {
            part[k] += __shfl_xor_sync(0xFFFFFFFF, part[k], 8);
            part[k] += __shfl_xor_sync(0xFFFFFFFF, part[k], 16);
        }
        float b2 = sm[O2_B2OUT];
        if (jg == 0) {
#pragma unroll
            for (int k = 0; k < 4; k++) {
                int n = nb + pg + 8 * k;
                if (n < N) out[n] = part[k] + b2;
            }
        }
        __syncwarp();
    }
}

// ---------------------------------------------------------------------------
extern "C" void kernel_launch(void* const* d_in, const int* in_sizes, int n_in,
                              void* d_out, int out_size) {
    const float* pts     = (const float*)d_in[0];
    const float* table   = (const float*)d_in[1];
    const float* s1_win  = (const float*)d_in[2];
    const float* s1_bin  = (const float*)d_in[3];
    const float* s1_wh   = (const float*)d_in[4];
    const float* s1_bh   = (const float*)d_in[5];
    const float* s1_wout = (const float*)d_in[6];
    const float* s1_bout = (const float*)d_in[7];
    const float* s2_win  = (const float*)d_in[8];
    const float* s2_bin  = (const float*)d_in[9];
    const float* s2_wh   = (const float*)d_in[10];
    const float* s2_bh   = (const float*)d_in[11];
    const float* s2_wout = (const float*)d_in[12];
    const float* s2_bout = (const float*)d_in[13];
    float* out = (float*)d_out;

    int N = in_sizes[0] / 3;

    // Resolutions in host double, EXACTLY mirroring numpy:
    Res8 R;
    double b = exp((log(4096.0) - log(16.0)) / 7.0);
    for (int l = 0; l < 8; l++) R.r[l] = (float)floor(16.0 * pow(b, (double)l));

    cudaFuncSetAttribute(mlp1_kernel, cudaFuncAttributeMaxDynamicSharedMemorySize,
                         (int)SM1_BYTES);
    cudaFuncSetAttribute(mlp2_kernel, cudaFuncAttributeMaxDynamicSharedMemorySize,
                         (int)SM2_BYTES);
    mlp1_kernel<<<NSM, TPB1, SM1_BYTES>>>(pts, table, s1_win, s1_bin, s1_wh,
                                          s1_bh, s1_wout, s1_bout, out, N, R);
    mlp2_kernel<<<NSM, TPB2, SM2_BYTES>>>(s2_win, s2_bin, s2_wh, s2_bh,
                                          s2_wout, s2_bout, out, N);
}

// round 17
// speedup vs baseline: 1.2136x; 1.2136x over previous
#include <cuda_runtime.h>
#include <math.h>

#define NP_MAX     1048576
#define TABLE_SIZE 524288
#define TMASK      (TABLE_SIZE - 1)
#define NUM_LEVELS 8
#define W0F        30.0f
#define NSM        148

#define TPB1       512
#define WARPS1     (TPB1 / 32)
#define TPB2       512
#define WARPS2     (TPB2 / 32)
#define XS1        68   // 17 odd 16B-chunks: conflict-free; >= 64 (layer outputs!)
#define XS2        68   // MUST be >= 64: hidden layers write 64 cols back into xs

typedef unsigned long long u64t;

// Encoding scratch, SoA: g_enc[c*N + n], c in [0,32)
__device__ float g_enc[NUM_LEVELS * 4 * NP_MAX];
// siren1 head output (o[0..15]) per point, lane-owned float4 chunks
__device__ float4 g_mid[NP_MAX * 4];

struct Res8 { float r[8]; };

// ---------------------------------------------------------------------------
// Packed f32x2 helpers (PTX-only; ptxas never auto-fuses FFMA2).
// ---------------------------------------------------------------------------
__device__ __forceinline__ u64t pack2(float x) {
    u64t r; unsigned xi = __float_as_uint(x);
    asm("mov.b64 %0, {%1, %1};" : "=l"(r) : "r"(xi));
    return r;
}
__device__ __forceinline__ u64t ffma2(u64t a, u64t b, u64t c) {
    u64t d;
    asm("fma.rn.f32x2 %0, %1, %2, %3;" : "=l"(d) : "l"(a), "l"(b), "l"(c));
    return d;
}
__device__ __forceinline__ float2 unpack2(u64t v) {
    unsigned lo, hi;
    asm("mov.b64 {%0, %1}, %2;" : "=r"(lo), "=r"(hi) : "l"(v));
    return make_float2(__uint_as_float(lo), __uint_as_float(hi));
}

// ---------------------------------------------------------------------------
// Accurate sin, ~1-2 ulp RELATIVE accuracy. Magic-number rounding is
// bit-identical to rintf(x*INV_PI) for |q| < 2^22; parity applied as
// sign-bit XOR (bit-identical to conditional negate). Validated R16.
// ---------------------------------------------------------------------------
__device__ __forceinline__ float sin_acc(float x) {
    const float INV_PI = 0.318309886183790672f;
    const float PI_HI  = 3.14159274101257324f;
    const float PI_LO  = -8.74227765734758577e-8f;
    const float MAGIC  = 12582912.0f;            // 1.5 * 2^23
    float t = __fadd_rn(__fmul_rn(x, INV_PI), MAGIC);
    unsigned sgn = __float_as_uint(t) << 31;     // parity of q -> sign bit
    float q = t - MAGIC;                         // == rintf(x * INV_PI)
    float r = fmaf(-q, PI_HI, x);
    r = fmaf(-q, PI_LO, r);
    float r2 = r * r;
    float p = 1.58969104521e-10f;
    p = fmaf(p, r2, -2.50507477726e-8f);
    p = fmaf(p, r2, 2.75573146014e-6f);
    p = fmaf(p, r2, -1.98412701138e-4f);
    p = fmaf(p, r2, 8.33333376795e-3f);
    p = fmaf(p, r2, -1.66666671634e-1f);
    float s = fmaf(p * r2, r, r);
    return __uint_as_float(__float_as_uint(s) ^ sgn);
}

// ---------------------------------------------------------------------------
// Kernel 1: Instant-NGP hash grid encoding (standalone: needs the HIGH
// occupancy of its own launch to hide 64 scattered gathers/point — fusing it
// into the 16-warp mlp1 cost ~500us in R16)
// ---------------------------------------------------------------------------
__global__ void hash_kernel(const float* __restrict__ pts,
                            const float* __restrict__ table,
                            int N, Res8 R) {
    int n = blockIdx.x * blockDim.x + threadIdx.x;
    if (n >= N) return;
    float px = (pts[3 * n + 0] + 1.0f) * 0.5f;
    float py = (pts[3 * n + 1] + 1.0f) * 0.5f;
    float pz = (pts[3 * n + 2] + 1.0f) * 0.5f;
    const float4* tab4 = (const float4*)table;
#pragma unroll
    for (int l = 0; l < NUM_LEVELS; l++) {
        float res = R.r[l];
        float sx = px * res, sy = py * res, sz = pz * res;
        float bx = floorf(sx), by = floorf(sy), bz = floorf(sz);
        float fx = sx - bx, fy = sy - by, fz = sz - bz;
        int ix = (int)bx, iy = (int)by, iz = (int)bz;
        unsigned hx0 = (unsigned)ix;
        unsigned hx1 = (unsigned)(ix + 1);
        unsigned hy0 = (unsigned)iy       * 2654435761u;
        unsigned hy1 = (unsigned)(iy + 1) * 2654435761u;
        unsigned hz0 = (unsigned)iz       * 805459861u;
        unsigned hz1 = (unsigned)(iz + 1) * 805459861u;
        const float4* t = tab4 + (size_t)l * TABLE_SIZE;
        float4 g000 = t[(hx0 ^ hy0 ^ hz0) & TMASK];
        float4 g001 = t[(hx0 ^ hy0 ^ hz1) & TMASK];
        float4 g010 = t[(hx0 ^ hy1 ^ hz0) & TMASK];
        float4 g011 = t[(hx0 ^ hy1 ^ hz1) & TMASK];
        float4 g100 = t[(hx1 ^ hy0 ^ hz0) & TMASK];
        float4 g101 = t[(hx1 ^ hy0 ^ hz1) & TMASK];
        float4 g110 = t[(hx1 ^ hy1 ^ hz0) & TMASK];
        float4 g111 = t[(hx1 ^ hy1 ^ hz1) & TMASK];
        float ux = 1.0f - fx, uy = 1.0f - fy, uz = 1.0f - fz;
        float w000 = ux * uy * uz, w001 = ux * uy * fz;
        float w010 = ux * fy * uz, w011 = ux * fy * fz;
        float w100 = fx * uy * uz, w101 = fx * uy * fz;
        float w110 = fx * fy * uz, w111 = fx * fy * fz;
        float a0 = w000 * g000.x + w001 * g001.x + w010 * g010.x + w011 * g011.x
                 + w100 * g100.x + w101 * g101.x + w110 * g110.x + w111 * g111.x;
        float a1 = w000 * g000.y + w001 * g001.y + w010 * g010.y + w011 * g011.y
                 + w100 * g100.y + w101 * g101.y + w110 * g110.y + w111 * g111.y;
        float a2 = w000 * g000.z + w001 * g001.z + w010 * g010.z + w011 * g011.z
                 + w100 * g100.z + w101 * g101.z + w110 * g110.z + w111 * g111.z;
        float a3 = w000 * g000.w + w001 * g001.w + w010 * g010.w + w011 * g011.w
                 + w100 * g100.w + w101 * g101.w + w110 * g110.w + w111 * g111.w;
        g_enc[(size_t)(l * 4 + 0) * N + n] = a0;
        g_enc[(size_t)(l * 4 + 1) * N + n] = a1;
        g_enc[(size_t)(l * 4 + 2) * N + n] = a2;
        g_enc[(size_t)(l * 4 + 3) * N + n] = a3;
    }
}

// ---------------------------------------------------------------------------
// Warp-tiled layer: warp = 32 points x 64 outputs.
// Lane (pg, jg): points {pg, pg+8, pg+16, pg+24}, outputs [16*jg, 16*jg+16).
// ---------------------------------------------------------------------------
template <int IN4, int STRIDE>
__device__ __forceinline__ void layer_tiled(const float* __restrict__ W,
                                            const float* __restrict__ B,
                                            float* __restrict__ xs,
                                            int pg, int jg, float scale) {
    u64t acc[4][8];
    {
        const ulonglong2* bb = (const ulonglong2*)(B + 16 * jg);
#pragma unroll
        for (int m = 0; m < 4; m++) {
            ulonglong2 b = bb[m];
#pragma unroll
            for (int k = 0; k < 4; k++) {
                acc[k][2 * m]     = b.x;
                acc[k][2 * m + 1] = b.y;
            }
        }
    }
    const float* wbase = W + 16 * jg;
    const float* x0p = xs + pg * STRIDE;
#pragma unroll 2
    for (int i4 = 0; i4 < IN4; i4++) {
        float4 xv[4];
#pragma unroll
        for (int k = 0; k < 4; k++)
            xv[k] = *(const float4*)(x0p + k * 8 * STRIDE + 4 * i4);
#pragma unroll
        for (int ii = 0; ii < 4; ii++) {
            const ulonglong2* wp = (const ulonglong2*)(wbase + (4 * i4 + ii) * 64);
            ulonglong2 wA = wp[0], wB = wp[1], wC = wp[2], wD = wp[3];
#pragma unroll
            for (int k = 0; k < 4; k++) {
                u64t x2 = pack2(((const float*)&xv[k])[ii]);
                acc[k][0] = ffma2(x2, wA.x, acc[k][0]);
                acc[k][1] = ffma2(x2, wA.y, acc[k][1]);
                acc[k][2] = ffma2(x2, wB.x, acc[k][2]);
                acc[k][3] = ffma2(x2, wB.y, acc[k][3]);
                acc[k][4] = ffma2(x2, wC.x, acc[k][4]);
                acc[k][5] = ffma2(x2, wC.y, acc[k][5]);
                acc[k][6] = ffma2(x2, wD.x, acc[k][6]);
                acc[k][7] = ffma2(x2, wD.y, acc[k][7]);
            }
        }
    }
    __syncwarp();
#pragma unroll
    for (int k = 0; k < 4; k++) {
        float* row = xs + (pg + 8 * k) * STRIDE + 16 * jg;
#pragma unroll
        for (int m = 0; m < 4; m++) {
            float2 v0 = unpack2(acc[k][2 * m]);
            float2 v1 = unpack2(acc[k][2 * m + 1]);
            float4 r;
            r.x = sin_acc(scale * v0.x);
            r.y = sin_acc(scale * v0.y);
            r.z = sin_acc(scale * v1.x);
            r.w = sin_acc(scale * v1.y);
            *(float4*)(row + 4 * m) = r;
        }
    }
    __syncwarp();
}

// SIREN1 head: 64 -> 16, no activation. Lane owns outputs [4jg, 4jg+4).
template <int STRIDE>
__device__ __forceinline__ void head16_tiled(const float* __restrict__ W,
                                             const float* __restrict__ B,
                                             const float* __restrict__ xs,
                                             int pg, int jg, float o[4][4]) {
    u64t acc[4][2];
    {
        const ulonglong2* bb = (const ulonglong2*)(B + 4 * jg);
        ulonglong2 b = bb[0];
#pragma unroll
        for (int k = 0; k < 4; k++) { acc[k][0] = b.x; acc[k][1] = b.y; }
    }
    const float* x0p = xs + pg * STRIDE;
#pragma unroll 2
    for (int i4 = 0; i4 < 16; i4++) {
        float4 xv[4];
#pragma unroll
        for (int k = 0; k < 4; k++)
            xv[k] = *(const float4*)(x0p + k * 8 * STRIDE + 4 * i4);
#pragma unroll
        for (int ii = 0; ii < 4; ii++) {
            const ulonglong2* wp = (const ulonglong2*)(W + (4 * i4 + ii) * 16 + 4 * jg);
            ulonglong2 w = wp[0];
#pragma unroll
            for (int k = 0; k < 4; k++) {
                u64t x2 = pack2(((const float*)&xv[k])[ii]);
                acc[k][0] = ffma2(x2, w.x, acc[k][0]);
                acc[k][1] = ffma2(x2, w.y, acc[k][1]);
            }
        }
    }
#pragma unroll
    for (int k = 0; k < 4; k++) {
        float2 v0 = unpack2(acc[k][0]);
        float2 v1 = unpack2(acc[k][1]);
        o[k][0] = v0.x; o[k][1] = v0.y; o[k][2] = v1.x; o[k][3] = v1.y;
    }
}

// ---------------------------------------------------------------------------
// Kernel 2: SIREN 1 (enc32 -> 64 -> 4x64 -> head16). Writes g_mid + density.
// ---------------------------------------------------------------------------
#define O1_W1IN  0        // 32*64 = 2048
#define O1_B1IN  2048     // 64
#define O1_W1H   2112     // 4*64*64 = 16384
#define O1_B1H   18496    // 4*64 = 256
#define O1_W1OUT 18752    // 64*16 = 1024
#define O1_B1OUT 19776    // 16
#define O1_XS    19792
#define SM1_BYTES ((O1_XS + WARPS1 * 32 * XS1) * sizeof(float))

__global__ void __launch_bounds__(TPB1, 1) mlp1_kernel(
    const float* __restrict__ s1_win,  const float* __restrict__ s1_bin,
    const float* __restrict__ s1_wh,   const float* __restrict__ s1_bh,
    const float* __restrict__ s1_wout, const float* __restrict__ s1_bout,
    float* __restrict__ out, int N) {
    extern __shared__ float sm[];
    int tid = threadIdx.x;
#define CPY(off, src, cnt) \
    for (int i = tid; i < (cnt); i += TPB1) sm[(off) + i] = (src)[i];
    CPY(O1_W1IN,  s1_win,  2048);
    CPY(O1_B1IN,  s1_bin,  64);
    CPY(O1_W1H,   s1_wh,   16384);
    CPY(O1_B1H,   s1_bh,   256);
    CPY(O1_W1OUT, s1_wout, 1024);
    CPY(O1_B1OUT, s1_bout, 16);
#undef CPY
    __syncthreads();

    int wid  = tid >> 5;
    int lane = tid & 31;
    int pg = lane & 7;
    int jg = lane >> 3;
    float* xs = sm + O1_XS + wid * (32 * XS1);

    int ntiles = (N + 31) >> 5;
    for (int t = blockIdx.x * WARPS1 + wid; t < ntiles; t += NSM * WARPS1) {
        int nb = t << 5;
        {
            int nl = min(nb + lane, N - 1);
            float* row = xs + lane * XS1;
#pragma unroll
            for (int c = 0; c < 32; c++) row[c] = g_enc[(size_t)c * N + nl];
        }
        __syncwarp();

        layer_tiled<8, XS1>(sm + O1_W1IN, sm + O1_B1IN, xs, pg, jg, W0F);
#pragma unroll
        for (int l = 0; l < 4; l++)
            layer_tiled<16, XS1>(sm + O1_W1H + l * 4096, sm + O1_B1H + l * 64,
                                 xs, pg, jg, 1.0f);

        float o[4][4];
        head16_tiled<XS1>(sm + O1_W1OUT, sm + O1_B1OUT, xs, pg, jg, o);

#pragma unroll
        for (int k = 0; k < 4; k++) {
            int n = nb + pg + 8 * k;
            if (n < N) {
                g_mid[(size_t)n * 4 + jg] =
                    make_float4(o[k][0], o[k][1], o[k][2], o[k][3]);
                if (jg == 0) out[N + n] = fmaxf(o[k][0], 0.0f);
            }
        }
        __syncwarp();
    }
}

// ---------------------------------------------------------------------------
// Kernel 3: SIREN 2 ([o1..15, enc32, 0pad] -> 64 -> 2x64 -> 1). Writes scalar.
// ---------------------------------------------------------------------------
#define O2_W2IN  0        // 48*64 = 3072 (row 47 zero-padded)
#define O2_B2IN  3072     // 64
#define O2_W2H   3136     // 2*64*64 = 8192
#define O2_B2H   11328    // 128
#define O2_W2OUT 11456    // 64
#define O2_B2OUT 11520    // 1 (+3 pad)
#define O2_XS    11524
#define SM2_BYTES ((O2_XS + WARPS2 * 32 * XS2) * sizeof(float))

__global__ void __launch_bounds__(TPB2, 1) mlp2_kernel(
    const float* __restrict__ s2_win,  const float* __restrict__ s2_bin,
    const float* __restrict__ s2_wh,   const float* __restrict__ s2_bh,
    const float* __restrict__ s2_wout, const float* __restrict__ s2_bout,
    float* __restrict__ out, int N) {
    extern __shared__ float sm[];
    int tid = threadIdx.x;
#define CPY(off, src, cnt) \
    for (int i = tid; i < (cnt); i += TPB2) sm[(off) + i] = (src)[i];
    CPY(O2_W2IN,  s2_win,  3008);
    CPY(O2_B2IN,  s2_bin,  64);
    CPY(O2_W2H,   s2_wh,   8192);
    CPY(O2_B2H,   s2_bh,   128);
    CPY(O2_W2OUT, s2_wout, 64);
    CPY(O2_B2OUT, s2_bout, 1);
#undef CPY
    for (int i = tid; i < 64; i += TPB2) sm[O2_W2IN + 47 * 64 + i] = 0.0f;
    __syncthreads();

    int wid  = tid >> 5;
    int lane = tid & 31;
    int pg = lane & 7;
    int jg = lane >> 3;
    float* xs = sm + O2_XS + wid * (32 * XS2);

    int ntiles = (N + 31) >> 5;
    for (int t = blockIdx.x * WARPS2 + wid; t < ntiles; t += NSM * WARPS2) {
        int nb = t << 5;

        // cols 0..14: o[1..15] from g_mid (lane reads its own chunk)
#pragma unroll
        for (int k = 0; k < 4; k++) {
            int n = min(nb + pg + 8 * k, N - 1);
            float4 v = g_mid[(size_t)n * 4 + jg];
            float* row = xs + (pg + 8 * k) * XS2;
            float vv[4] = {v.x, v.y, v.z, v.w};
#pragma unroll
            for (int c = 0; c < 4; c++) {
                int j = 4 * jg + c;
                if (j >= 1) row[j - 1] = vv[c];
            }
        }
        // cols 15..46: enc; col 47: 0
        {
            int nl = min(nb + lane, N - 1);
            float* row = xs + lane * XS2;
#pragma unroll
            for (int c = 0; c < 32; c++) row[15 + c] = g_enc[(size_t)c * N + nl];
            row[47] = 0.0f;
        }
        __syncwarp();

        layer_tiled<12, XS2>(sm + O2_W2IN, sm + O2_B2IN, xs, pg, jg, W0F);
#pragma unroll
        for (int l = 0; l < 2; l++)
            layer_tiled<16, XS2>(sm + O2_W2H + l * 4096, sm + O2_B2H + l * 64,
                                 xs, pg, jg, 1.0f);

        // 64 -> 1: lane sums i in [16jg,16jg+16), butterfly across jg lanes
        float part[4] = {0.0f, 0.0f, 0.0f, 0.0f};
        const float* wv  = sm + O2_W2OUT + 16 * jg;
        const float* x0p = xs + pg * XS2 + 16 * jg;
#pragma unroll
        for (int q = 0; q < 4; q++) {
            float4 w = *(const float4*)(wv + 4 * q);
#pragma unroll
            for (int k = 0; k < 4; k++) {
                float4 x = *(const float4*)(x0p + k * 8 * XS2 + 4 * q);
                part[k] = fmaf(x.x, w.x, part[k]);
                part[k] = fmaf(x.y, w.y, part[k]);
                part[k] = fmaf(x.z, w.z, part[k]);
                part[k] = fmaf(x.w, w.w, part[k]);
            }
        }
#pragma unroll
        for (int k = 0; k < 4; k++) {
            part[k] += __shfl_xor_sync(0xFFFFFFFF, part[k], 8);
            part[k] += __shfl_xor_sync(0xFFFFFFFF, part[k], 16);
        }
        float b2 = sm[O2_B2OUT];
        if (jg == 0) {
#pragma unroll
            for (int k = 0; k < 4; k++) {
                int n = nb + pg + 8 * k;
                if (n < N) out[n] = part[k] + b2;
            }
        }
        __syncwarp();
    }
}

// ---------------------------------------------------------------------------
extern "C" void kernel_launch(void* const* d_in, const int* in_sizes, int n_in,
                              void* d_out, int out_size) {
    const float* pts     = (const float*)d_in[0];
    const float* table   = (const float*)d_in[1];
    const float* s1_win  = (const float*)d_in[2];
    const float* s1_bin  = (const float*)d_in[3];
    const float* s1_wh   = (const float*)d_in[4];
    const float* s1_bh   = (const float*)d_in[5];
    const float* s1_wout = (const float*)d_in[6];
    const float* s1_bout = (const float*)d_in[7];
    const float* s2_win  = (const float*)d_in[8];
    const float* s2_bin  = (const float*)d_in[9];
    const float* s2_wh   = (const float*)d_in[10];
    const float* s2_bh   = (const float*)d_in[11];
    const float* s2_wout = (const float*)d_in[12];
    const float* s2_bout = (const float*)d_in[13];
    float* out = (float*)d_out;

    int N = in_sizes[0] / 3;

    // Resolutions in host double, EXACTLY mirroring numpy:
    Res8 R;
    double b = exp((log(4096.0) - log(16.0)) / 7.0);
    for (int l = 0; l < 8; l++) R.r[l] = (float)floor(16.0 * pow(b, (double)l));

    hash_kernel<<<(N + 255) / 256, 256>>>(pts, table, N, R);

    cudaFuncSetAttribute(mlp1_kernel, cudaFuncAttributeMaxDynamicSharedMemorySize,
                         (int)SM1_BYTES);
    cudaFuncSetAttribute(mlp2_kernel, cudaFuncAttributeMaxDynamicSharedMemorySize,
                         (int)SM2_BYTES);
    mlp1_kernel<<<NSM, TPB1, SM1_BYTES>>>(s1_win, s1_bin, s1_wh, s1_bh,
                                          s1_wout, s1_bout, out, N);
    mlp2_kernel<<<NSM, TPB2, SM2_BYTES>>>(s2_win, s2_bin, s2_wh, s2_bh,
                                          s2_wout, s2_bout, out, N);
}